// round 17
// baseline (speedup 1.0000x reference)
#include <cuda_runtime.h>
#include <cuda_fp16.h>
#include <cstdint>
#include <math.h>

#define NB 2
#define NT 4096
#define ND 2048
#define NH 32
#define NN 64
#define NP 64
#define NL 256
#define NC 16
#define NTOK (NB*NT)   // 8192

// swizzled [64][64] accessor (A-frag tiles): 4-group-preserving, conflict-free
#define SW(r,c) (((r)<<6) + ((c) ^ (((r)&15)<<2)))
// pad-72 k-major tiles: conflict-free transposed fragment gathers
#define P72 72

// ---------------- scratch (device globals; no runtime allocation) ----------
__device__ float g_B[(size_t)NTOK*NN];
__device__ float g_C[(size_t)NTOK*NN];
__device__ float g_dt[(size_t)NTOK*NH];
__device__ float g_cum[(size_t)NB*NH*NC*NL];
__device__ float g_states[(size_t)NB*NC*NH*NN*NP];
__device__ float g_prev[(size_t)NB*NC*NH*NN*NP];
__device__ float g_Y[(size_t)NTOK*ND];

__device__ __forceinline__ float softplus_f(float v) {
    return v > 20.f ? v : log1pf(expf(v));
}

__device__ __forceinline__ float to_tf32(float v) {
    uint32_t u;
    asm("cvt.rna.tf32.f32 %0, %1;" : "=r"(u) : "f"(v));
    return __uint_as_float(u);
}

__device__ __forceinline__ float4 tf32x4(float4 v) {
    return make_float4(to_tf32(v.x), to_tf32(v.y), to_tf32(v.z), to_tf32(v.w));
}

__device__ __forceinline__ void mma_tf32(float* d, const uint32_t* a, const uint32_t* b) {
    asm volatile(
        "mma.sync.aligned.m16n8k8.row.col.f32.tf32.tf32.f32 "
        "{%0,%1,%2,%3}, {%4,%5,%6,%7}, {%8,%9}, {%0,%1,%2,%3};"
        : "+f"(d[0]), "+f"(d[1]), "+f"(d[2]), "+f"(d[3])
        : "r"(a[0]), "r"(a[1]), "r"(a[2]), "r"(a[3]),
          "r"(b[0]), "r"(b[1]));
}

__device__ __forceinline__ void mma_f16(float* d, const uint32_t* a, const uint32_t* b) {
    asm volatile(
        "mma.sync.aligned.m16n8k16.row.col.f32.f16.f16.f32 "
        "{%0,%1,%2,%3}, {%4,%5,%6,%7}, {%8,%9}, {%0,%1,%2,%3};"
        : "+f"(d[0]), "+f"(d[1]), "+f"(d[2]), "+f"(d[3])
        : "r"(a[0]), "r"(a[1]), "r"(a[2]), "r"(a[3]),
          "r"(b[0]), "r"(b[1]));
}

__device__ __forceinline__ uint32_t smem_u32(const void* p) {
    uint32_t a;
    asm("{ .reg .u64 t; cvta.to.shared.u64 t, %1; cvt.u32.u64 %0, t; }"
        : "=r"(a) : "l"(p));
    return a;
}

__device__ __forceinline__ void ldsm_x4(uint32_t* r, uint32_t addr) {
    asm volatile("ldmatrix.sync.aligned.m8n8.x4.shared.b16 {%0,%1,%2,%3}, [%4];"
        : "=r"(r[0]), "=r"(r[1]), "=r"(r[2]), "=r"(r[3]) : "r"(addr));
}

// ---------------------------------------------------------------------------
// Fused projections, one launch: grid (128, 3)  (proven R13)
// ---------------------------------------------------------------------------
__global__ __launch_bounds__(256) void proj_fused(
    const float* __restrict__ x,
    const float* __restrict__ B_w, const float* __restrict__ B_b,
    const float* __restrict__ C_w, const float* __restrict__ C_b,
    const float* __restrict__ dt_w, const float* __restrict__ dt_b)
{
    __shared__ float sm[4608];
    const int tid = threadIdx.x;
    const int m0 = blockIdx.x * 64;

    if (blockIdx.y < 2) {
        float* As = sm;
        float* Ws = sm + 2304;
        const int wid = tid >> 5, lane = tid & 31;
        const int wm = wid >> 2, wn = wid & 3;
        const int lg = lane >> 2, lq = lane & 3;
        const int osel = blockIdx.y;
        const float* W = osel ? C_w : B_w;
        const float* bias = osel ? C_b : B_b;
        float* out = osel ? g_C : g_B;

        float acc[2][2][4];
        #pragma unroll
        for (int i = 0; i < 2; i++)
            #pragma unroll
            for (int j = 0; j < 2; j++)
                #pragma unroll
                for (int q = 0; q < 4; q++) acc[i][j][q] = 0.f;

        for (int k0 = 0; k0 < ND; k0 += 32) {
            int v = tid;
            #pragma unroll
            for (int it = 0; it < 2; it++, v += 256) {
                int row = v >> 3, c4 = (v & 7) * 4;
                float4 av = *(const float4*)&x[(size_t)(m0 + row) * ND + k0 + c4];
                *(float4*)&As[row*36 + c4] = tf32x4(av);
                float4 wv = *(const float4*)&W[(size_t)row * ND + k0 + c4];
                *(float4*)&Ws[row*36 + c4] = tf32x4(wv);
            }
            __syncthreads();
            #pragma unroll
            for (int kk = 0; kk < 32; kk += 8) {
                uint32_t af[2][4], bf[2][2];
                #pragma unroll
                for (int i = 0; i < 2; i++) {
                    int r = wm*32 + i*16 + lg;
                    af[i][0] = __float_as_uint(As[r*36 + kk + lq]);
                    af[i][1] = __float_as_uint(As[(r+8)*36 + kk + lq]);
                    af[i][2] = __float_as_uint(As[r*36 + kk + 4 + lq]);
                    af[i][3] = __float_as_uint(As[(r+8)*36 + kk + 4 + lq]);
                }
                #pragma unroll
                for (int j = 0; j < 2; j++) {
                    int n = wn*16 + j*8 + lg;
                    bf[j][0] = __float_as_uint(Ws[n*36 + kk + lq]);
                    bf[j][1] = __float_as_uint(Ws[n*36 + kk + 4 + lq]);
                }
                #pragma unroll
                for (int i = 0; i < 2; i++)
                    #pragma unroll
                    for (int j = 0; j < 2; j++)
                        mma_tf32(acc[i][j], af[i], bf[j]);
            }
            __syncthreads();
        }
        #pragma unroll
        for (int i = 0; i < 2; i++) {
            int r = m0 + wm*32 + i*16 + lg;
            #pragma unroll
            for (int j = 0; j < 2; j++) {
                int n = wn*16 + j*8 + 2*lq;
                float b0 = bias[n], b1 = bias[n+1];
                out[(size_t)r*64 + n]       = acc[i][j][0] + b0;
                out[(size_t)r*64 + n + 1]   = acc[i][j][1] + b1;
                out[(size_t)(r+8)*64 + n]   = acc[i][j][2] + b0;
                out[(size_t)(r+8)*64 + n+1] = acc[i][j][3] + b1;
            }
        }
    } else {
        float* Asd = sm;
        float* Wsd = sm + 2176;
        const int tn = tid & 15, tm = tid >> 4;
        float acc[4][2] = {};

        for (int k0 = 0; k0 < ND; k0 += 32) {
            int v = tid;
            #pragma unroll
            for (int it = 0; it < 2; it++, v += 256) {
                int row = v >> 3, c4 = (v & 7) * 4;
                float4 av = *(const float4*)&x[(size_t)(m0 + row) * ND + k0 + c4];
                Asd[(c4+0)*68 + row] = av.x;
                Asd[(c4+1)*68 + row] = av.y;
                Asd[(c4+2)*68 + row] = av.z;
                Asd[(c4+3)*68 + row] = av.w;
            }
            {
                int row = tid >> 3, c4 = (tid & 7) * 4;
                float4 wv = *(const float4*)&dt_w[(size_t)row * ND + k0 + c4];
                Wsd[(c4+0)*68 + row] = wv.x;
                Wsd[(c4+1)*68 + row] = wv.y;
                Wsd[(c4+2)*68 + row] = wv.z;
                Wsd[(c4+3)*68 + row] = wv.w;
            }
            __syncthreads();
            #pragma unroll
            for (int k = 0; k < 32; k++) {
                float a[4], b[2];
                #pragma unroll
                for (int i = 0; i < 4; i++) a[i] = Asd[k*68 + tm*4 + i];
                b[0] = Wsd[k*68 + tn*2];
                b[1] = Wsd[k*68 + tn*2 + 1];
                #pragma unroll
                for (int i = 0; i < 4; i++) {
                    acc[i][0] = fmaf(a[i], b[0], acc[i][0]);
                    acc[i][1] = fmaf(a[i], b[1], acc[i][1]);
                }
            }
            __syncthreads();
        }
        #pragma unroll
        for (int i = 0; i < 4; i++)
            #pragma unroll
            for (int j = 0; j < 2; j++) {
                int m = m0 + tm*4 + i, n = tn*2 + j;
                g_dt[(size_t)m * NH + n] = softplus_f(acc[i][j] + dt_b[n]);
            }
    }
}

// ---------------------------------------------------------------------------
// Per-(b,h,c) inclusive cumsum of dA = dt * A  over the chunk (L=256)
// ---------------------------------------------------------------------------
__global__ void cumsum_kernel(const float* __restrict__ A_log)
{
    __shared__ float sm[NL];
    int bid = blockIdx.x;
    int c = bid % NC, h = (bid / NC) % NH, b = bid / (NC * NH);
    int s = threadIdx.x;
    float Ah = -expf(A_log[h]);
    int t = c * NL + s;
    sm[s] = g_dt[(size_t)(b*NT + t)*NH + h] * Ah;
    __syncthreads();
    for (int off = 1; off < NL; off <<= 1) {
        float add = (s >= off) ? sm[s - off] : 0.f;
        __syncthreads();
        sm[s] += add;
        __syncthreads();
    }
    g_cum[(size_t)bid * NL + s] = sm[s];
}

// ---------------------------------------------------------------------------
// Chunk states, 1xTF32 mma, pad-72 tiles (proven R10)
// ---------------------------------------------------------------------------
__global__ __launch_bounds__(256) void states_tc(const float* __restrict__ x)
{
    __shared__ float BT[64*P72];
    __shared__ float XS[64*P72];
    int bid = blockIdx.x;
    int h = bid % NH, c = (bid / NH) % NC, b = bid / (NH*NC);
    const int tid = threadIdx.x;
    const int wid = tid >> 5, lane = tid & 31;
    const int wm = wid >> 1, wn = wid & 1;
    const int lg = lane >> 2, lq = lane & 3;
    const float* cumc = &g_cum[(size_t)((b*NH + h)*NC + c) * NL];
    const float cum_last = cumc[NL-1];
    const int lr0 = wm*16 + lg;

    float acc[4][4];
    #pragma unroll
    for (int j = 0; j < 4; j++)
        #pragma unroll
        for (int q = 0; q < 4; q++) acc[j][q] = 0.f;

    for (int s0 = 0; s0 < NL; s0 += 64) {
        if (s0) __syncthreads();
        int v = tid;
        #pragma unroll
        for (int it = 0; it < 4; it++, v += 256) {
            int row = v >> 4, c4 = (v & 15) * 4;
            int gt = c*NL + s0 + row;
            float w = __expf(cum_last - cumc[s0 + row]) *
                      g_dt[(size_t)(b*NT + gt)*NH + h];
            float4 bv = *(const float4*)&g_B[(size_t)(b*NT + gt)*NN + c4];
            float4 xv = *(const float4*)&x[(size_t)(b*NT + gt)*ND + h*NP + c4];
            *(float4*)&BT[row*P72 + c4] =
                make_float4(to_tf32(bv.x*w), to_tf32(bv.y*w),
                            to_tf32(bv.z*w), to_tf32(bv.w*w));
            *(float4*)&XS[row*P72 + c4] = tf32x4(xv);
        }
        __syncthreads();
        #pragma unroll
        for (int kk = 0; kk < 64; kk += 8) {
            uint32_t ah[4];
            ah[0] = __float_as_uint(BT[(kk+lq)*P72   + lr0]);
            ah[1] = __float_as_uint(BT[(kk+lq)*P72   + lr0 + 8]);
            ah[2] = __float_as_uint(BT[(kk+4+lq)*P72 + lr0]);
            ah[3] = __float_as_uint(BT[(kk+4+lq)*P72 + lr0 + 8]);
            #pragma unroll
            for (int j = 0; j < 4; j++) {
                int p = wn*32 + j*8 + lg;
                uint32_t bh[2];
                bh[0] = __float_as_uint(XS[(kk+lq)*P72   + p]);
                bh[1] = __float_as_uint(XS[(kk+4+lq)*P72 + p]);
                mma_tf32(acc[j], ah, bh);
            }
        }
    }
    float* S = &g_states[(((size_t)b*NC + c)*NH + h) * (NN*NP)];
    #pragma unroll
    for (int j = 0; j < 4; j++) {
        int p = wn*32 + j*8 + 2*lq;
        S[(size_t)lr0*NP + p]         = acc[j][0];
        S[(size_t)lr0*NP + p + 1]     = acc[j][1];
        S[(size_t)(lr0+8)*NP + p]     = acc[j][2];
        S[(size_t)(lr0+8)*NP + p + 1] = acc[j][3];
    }
}

// ---------------------------------------------------------------------------
// Inter-chunk scan, element-parallel, software-pipelined loads
// ---------------------------------------------------------------------------
__global__ void scan_kernel()
{
    int bid = blockIdx.x;
    int ec = bid & 15;
    int bh = bid >> 4;
    int h = bh % NH, b = bh / NH;
    int e = ec * 256 + threadIdx.x;

    float dec[NC];
    #pragma unroll
    for (int c = 0; c < NC; c++)
        dec[c] = __expf(g_cum[(size_t)((b*NH + h)*NC + c)*NL + NL - 1]);

    size_t base = (((size_t)b*NC)*NH + h) * (NN*NP) + e;
    const size_t cstr = (size_t)NH * NN * NP;
    float R = 0.f;
    float sv = g_states[base];
    #pragma unroll
    for (int c = 0; c < NC; c++) {
        g_prev[base + (size_t)c*cstr] = R;
        float nxt = (c + 1 < NC) ? g_states[base + (size_t)(c+1)*cstr] : 0.f;
        R = fmaf(dec[c], R, sv);
        sv = nxt;
    }
}

// ---------------------------------------------------------------------------
// Y kernel, merged l-tile pairs + ldmatrix (proven R13)
// ---------------------------------------------------------------------------
#define Y_SMEM ((5*4096 + 64*P72 + 64)*4)
__global__ __launch_bounds__(256) void y_kernel_tc(const float* __restrict__ x,
                                                   const float* __restrict__ Dvec)
{
    extern __shared__ float ysm[];
    float* Cs  = ysm;
    float* BG  = ysm + 8192;
    float* GS  = ysm + 12288;
    float* XT  = ysm + 20480;
    float* ES  = ysm + 20480 + 64*P72;

    int bid = blockIdx.x;
    int pr = bid & 1;
    int h  = (bid >> 1) & 31;
    int c  = (bid >> 6) & 15;
    int b  = bid >> 10;
    const int lt0 = pr*2, lt1 = lt0 + 1;
    const int tid = threadIdx.x;
    const int wid = tid >> 5, lane = tid & 31;
    const int wm = wid >> 1, wn = wid & 1;
    const int lg = lane >> 2, lq = lane & 3;
    const int t0 = c * NL;
    const float* cumc = &g_cum[(size_t)((b*NH + h)*NC + c) * NL];

    const int lrow8 = lane & 7;
    const int aR  = wm*16 + ((lane >> 3) & 1)*8 + lrow8;
    const uint32_t aXor = (uint32_t)((aR & 15) << 2);
    const uint32_t aCb  = (uint32_t)(((lane >> 4) & 1) * 4);
    const uint32_t csA0 = smem_u32(Cs) + (uint32_t)aR*256u;
    const uint32_t gsA0 = smem_u32(GS) + (uint32_t)aR*256u;
    const int bmid = lane >> 3;
    const int bR   = wn*32 + ((bmid >> 1) & 1)*8 + lrow8;
    const uint32_t bXor = (uint32_t)((bR & 15) << 2);
    const uint32_t bCb  = (uint32_t)((bmid & 1) * 4);
    const uint32_t bgB0 = smem_u32(BG) + (uint32_t)bR*256u;

    {
        const float* S = &g_prev[(((size_t)b*NC + c)*NH + h) * (NN*NP)];
        #pragma unroll
        for (int t = 0; t < 2; t++) {
            int v = tid;
            #pragma unroll
            for (int it = 0; it < 4; it++, v += 256) {
                int row = v >> 4, c4 = (v & 15) * 4;
                float4 cv = *(const float4*)
                    &g_C[(size_t)(b*NT + t0 + (lt0+t)*64 + row)*NN + c4];
                *(float4*)&Cs[t*4096 + SW(row, c4)] = tf32x4(cv);
            }
        }
        int v = tid;
        #pragma unroll
        for (int it = 0; it < 4; it++, v += 256) {
            int row = v >> 4, c4 = (v & 15) * 4;
            float4 sv = *(const float4*)&S[row*64 + c4];
            *(float4*)&XT[row*P72 + c4] = tf32x4(sv);
        }
    }
    __syncthreads();

    const int lr0 = wm*16 + lg;
    float cl[2][2];
    #pragma unroll
    for (int t = 0; t < 2; t++) {
        cl[t][0] = cumc[(lt0+t)*64 + lr0];
        cl[t][1] = cumc[(lt0+t)*64 + lr0 + 8];
    }

    float acc[2][4][4];
    #pragma unroll
    for (int t = 0; t < 2; t++)
        #pragma unroll
        for (int j = 0; j < 4; j++)
            #pragma unroll
            for (int q = 0; q < 4; q++) acc[t][j][q] = 0.f;

    #pragma unroll
    for (int t = 0; t < 2; t++) {
        const uint32_t ctA = csA0 + (uint32_t)t*16384u;
        #pragma unroll
        for (int kk = 0; kk < 64; kk += 8) {
            uint32_t ah[4];
            ldsm_x4(ah, ctA + ((((uint32_t)kk | aCb) ^ aXor) << 2));
            #pragma unroll
            for (int j = 0; j < 4; j++) {
                int p = wn*32 + j*8 + lg;
                uint32_t bh[2];
                bh[0] = __float_as_uint(XT[(kk+lq)*P72   + p]);
                bh[1] = __float_as_uint(XT[(kk+4+lq)*P72 + p]);
                mma_tf32(acc[t][j], ah, bh);
            }
        }
        float e0 = __expf(cl[t][0]), e1 = __expf(cl[t][1]);
        #pragma unroll
        for (int j = 0; j < 4; j++) {
            acc[t][j][0] *= e0; acc[t][j][1] *= e0;
            acc[t][j][2] *= e1; acc[t][j][3] *= e1;
        }
    }

    for (int st = 0; st <= lt1; st++) {
        const float m = cumc[st*64 + 63];
        __syncthreads();
        {
            int v = tid;
            #pragma unroll
            for (int it = 0; it < 4; it++, v += 256) {
                int row = v >> 4, c4 = (v & 15) * 4;
                int gt = t0 + st*64 + row;
                float4 bv = *(const float4*)&g_B[(size_t)(b*NT + gt)*NN + c4];
                *(float4*)&BG[SW(row, c4)] = tf32x4(bv);
                float sc = g_dt[(size_t)(b*NT + gt)*NH + h];
                float4 xv = *(const float4*)&x[(size_t)(b*NT + gt)*ND + h*NP + c4];
                *(float4*)&XT[row*P72 + c4] =
                    make_float4(to_tf32(xv.x*sc), to_tf32(xv.y*sc),
                                to_tf32(xv.z*sc), to_tf32(xv.w*sc));
            }
            if (tid < 64) ES[tid] = __expf(m - cumc[st*64 + tid]);
        }
        __syncthreads();

        #pragma unroll
        for (int t = 0; t < 2; t++) {
            int lt = lt0 + t;
            if (st > lt) continue;
            const uint32_t ctA = csA0 + (uint32_t)t*16384u;
            float ga[4][4];
            #pragma unroll
            for (int j = 0; j < 4; j++)
                #pragma unroll
                for (int q = 0; q < 4; q++) ga[j][q] = 0.f;
            #pragma unroll
            for (int kk = 0; kk < 64; kk += 8) {
                uint32_t ah[4];
                ldsm_x4(ah, ctA + ((((uint32_t)kk | aCb) ^ aXor) << 2));
                uint32_t bfr[4][2];
                #pragma unroll
                for (int jp = 0; jp < 2; jp++) {
                    uint32_t bt[4];
                    ldsm_x4(bt, bgB0 + (uint32_t)jp*4096u
                                + ((((uint32_t)kk | bCb) ^ bXor) << 2));
                    bfr[2*jp][0]   = bt[0]; bfr[2*jp][1]   = bt[1];
                    bfr[2*jp+1][0] = bt[2]; bfr[2*jp+1][1] = bt[3];
                }
                #pragma unroll
                for (int j = 0; j < 4; j++)
                    mma_tf32(ga[j], ah, bfr[j]);
            }
            if (st == lt) {
                int l0 = lr0, l1 = lr0 + 8;
                #pragma unroll
                for (int j = 0; j < 4; j++) {
                    int s0c = wn*32 + j*8 + 2*lq;
                    float cs0 = cumc[st*64 + s0c];
                    float cs1 = cumc[st*64 + s0c + 1];
                    ga[j][0] = (s0c     <= l0) ? ga[j][0] * __expf(cl[t][0] - cs0) : 0.f;
                    ga[j][1] = (s0c + 1 <= l0) ? ga[j][1] * __expf(cl[t][0] - cs1) : 0.f;
                    ga[j][2] = (s0c     <= l1) ? ga[j][2] * __expf(cl[t][1] - cs0) : 0.f;
                    ga[j][3] = (s0c + 1 <= l1) ? ga[j][3] * __expf(cl[t][1] - cs1) : 0.f;
                }
            } else {
                #pragma unroll
                for (int j = 0; j < 4; j++) {
                    int s0c = wn*32 + j*8 + 2*lq;
                    float e0 = ES[s0c], e1 = ES[s0c + 1];
                    ga[j][0] *= e0; ga[j][1] *= e1;
                    ga[j][2] *= e0; ga[j][3] *= e1;
                }
            }
            float* Gt = GS + t*4096;
            #pragma unroll
            for (int j = 0; j < 4; j++) {
                int col = wn*32 + j*8 + 2*lq;
                Gt[SW(lr0,   col)]     = to_tf32(ga[j][0]);
                Gt[SW(lr0,   col + 1)] = to_tf32(ga[j][1]);
                Gt[SW(lr0+8, col)]     = to_tf32(ga[j][2]);
                Gt[SW(lr0+8, col + 1)] = to_tf32(ga[j][3]);
            }
        }
        __syncthreads();

        #pragma unroll
        for (int t = 0; t < 2; t++) {
            int lt = lt0 + t;
            if (st > lt) continue;
            const uint32_t gtA = gsA0 + (uint32_t)t*16384u;
            if (st == lt) {
                #pragma unroll
                for (int kk = 0; kk < 64; kk += 8) {
                    uint32_t ah[4];
                    ldsm_x4(ah, gtA + ((((uint32_t)kk | aCb) ^ aXor) << 2));
                    #pragma unroll
                    for (int j = 0; j < 4; j++) {
                        int p = wn*32 + j*8 + lg;
                        uint32_t bh[2];
                        bh[0] = __float_as_uint(XT[(kk+lq)*P72   + p]);
                        bh[1] = __float_as_uint(XT[(kk+4+lq)*P72 + p]);
                        mma_tf32(acc[t][j], ah, bh);
                    }
                }
            } else {
                float ga[4][4];
                #pragma unroll
                for (int j = 0; j < 4; j++)
                    #pragma unroll
                    for (int q = 0; q < 4; q++) ga[j][q] = 0.f;
                #pragma unroll
                for (int kk = 0; kk < 64; kk += 8) {
                    uint32_t ah[4];
                    ldsm_x4(ah, gtA + ((((uint32_t)kk | aCb) ^ aXor) << 2));
                    #pragma unroll
                    for (int j = 0; j < 4; j++) {
                        int p = wn*32 + j*8 + lg;
                        uint32_t bh[2];
                        bh[0] = __float_as_uint(XT[(kk+lq)*P72   + p]);
                        bh[1] = __float_as_uint(XT[(kk+4+lq)*P72 + p]);
                        mma_tf32(ga[j], ah, bh);
                    }
                }
                float e0 = __expf(cl[t][0] - m), e1 = __expf(cl[t][1] - m);
                #pragma unroll
                for (int j = 0; j < 4; j++) {
                    acc[t][j][0] = fmaf(e0, ga[j][0], acc[t][j][0]);
                    acc[t][j][1] = fmaf(e0, ga[j][1], acc[t][j][1]);
                    acc[t][j][2] = fmaf(e1, ga[j][2], acc[t][j][2]);
                    acc[t][j][3] = fmaf(e1, ga[j][3], acc[t][j][3]);
                }
            }
        }
    }

    float Dh = Dvec[h];
    #pragma unroll
    for (int t = 0; t < 2; t++) {
        int gt0 = t0 + (lt0+t)*64 + lr0;
        #pragma unroll
        for (int j = 0; j < 4; j++) {
            int p = wn*32 + j*8 + 2*lq;
            size_t o0 = (size_t)(b*NT + gt0)*ND + h*NP + p;
            size_t o1 = o0 + (size_t)8*ND;
            g_Y[o0]     = acc[t][j][0] + Dh * x[o0];
            g_Y[o0 + 1] = acc[t][j][1] + Dh * x[o0 + 1];
            g_Y[o1]     = acc[t][j][2] + Dh * x[o1];
            g_Y[o1 + 1] = acc[t][j][3] + Dh * x[o1 + 1];
        }
    }
}

// ---------------------------------------------------------------------------
// Output projection, FP16 m16n8k16 mma, ping-pong double-buffered:
// per slab: issue LDG(next) -> mma(buf p) -> STS(buf p^1) -> ONE sync.
// smem half[2][128][40] = 40KB.
// ---------------------------------------------------------------------------
#define OGBUF (128*40*2)   // bytes per buffer
__global__ __launch_bounds__(256) void out_gemm_f16(
    const float* __restrict__ W, const float* __restrict__ bias,
    float* __restrict__ out)
{
    __shared__ __half As[2][128][40];
    __shared__ __half Ws[2][128][40];
    const int tid  = threadIdx.x;
    const int wid  = tid >> 5, lane = tid & 31;
    const int warp_m = wid >> 2, warp_n = wid & 3;   // 2 x 4
    const int m0 = blockIdx.y * 128, n0 = blockIdx.x * 128;
    const int qrow = tid >> 3;
    const int qc4  = (tid & 7) * 4;
    const int lg = lane >> 2, lq = lane & 3;
    const float* A = g_Y;

    const int lrow8 = lane & 7;
    const int aRow = warp_m*64 + ((lane >> 3) & 1)*8 + lrow8;
    const int aColH = ((lane >> 4) & 1)*8;
    const uint32_t baseA = smem_u32(As) + (uint32_t)(aRow*40 + aColH)*2u;
    const int bmid = lane >> 3;
    const int bRow = warp_n*32 + ((bmid >> 1) & 1)*8 + lrow8;
    const int bColH = (bmid & 1)*8;
    const uint32_t baseB = smem_u32(Ws) + (uint32_t)(bRow*40 + bColH)*2u;

    float acc[4][4][4];
    #pragma unroll
    for (int i = 0; i < 4; i++)
        #pragma unroll
        for (int j = 0; j < 4; j++)
            #pragma unroll
            for (int q = 0; q < 4; q++) acc[i][j][q] = 0.f;

    float4 pa[4], pw[4];
    #pragma unroll
    for (int it = 0; it < 4; it++) {
        int r = qrow + it * 32;
        pa[it] = *(const float4*)&A[(size_t)(m0 + r) * ND + qc4];
        pw[it] = *(const float4*)&W[(size_t)(n0 + r) * ND + qc4];
    }
    // fill buffer 0
    #pragma unroll
    for (int it = 0; it < 4; it++) {
        int r = qrow + it * 32;
        *(__half2*)&As[0][r][qc4]     = __floats2half2_rn(pa[it].x, pa[it].y);
        *(__half2*)&As[0][r][qc4 + 2] = __floats2half2_rn(pa[it].z, pa[it].w);
        *(__half2*)&Ws[0][r][qc4]     = __floats2half2_rn(pw[it].x, pw[it].y);
        *(__half2*)&Ws[0][r][qc4 + 2] = __floats2half2_rn(pw[it].z, pw[it].w);
    }
    __syncthreads();

    int p = 0;
    for (int k0 = 0; k0 < ND; k0 += 32) {
        const bool has_next = (k0 + 32 < ND);
        if (has_next) {
            #pragma unroll
            for (int it = 0; it < 4; it++) {
                int r = qrow + it * 32;
                pa[it] = *(const float4*)&A[(size_t)(m0 + r) * ND + k0 + 32 + qc4];
                pw[it] = *(const float4*)&W[(size_t)(n0 + r) * ND + k0 + 32 + qc4];
            }
        }

        const uint32_t bufOff = (uint32_t)p * OGBUF;
        #pragma unroll
        for (int kk = 0; kk < 32; kk += 16) {
            uint32_t afr[4][4], bfr[4][2];
            #pragma unroll
            for (int i = 0; i < 4; i++)
                ldsm_x4(afr[i], baseA + bufOff + (uint32_t)(i*16*40 + kk)*2u);
            #pragma unroll
            for (int jp = 0; jp < 2; jp++) {
                uint32_t bt[4];
                ldsm_x4(bt, baseB + bufOff + (uint32_t)(jp*16*40 + kk)*2u);
                bfr[2*jp][0]   = bt[0]; bfr[2*jp][1]   = bt[1];
                bfr[2*jp+1][0] = bt[2]; bfr[2*jp+1][1] = bt[3];
            }
            #pragma unroll
            for (int i = 0; i < 4; i++)
                #pragma unroll
                for (int j = 0; j < 4; j++)
                    mma_f16(acc[i][j], afr[i], bfr[j]);
        }

        if (has_next) {
            int np = p ^ 1;
            #pragma unroll
            for (int it = 0; it < 4; it++) {
                int r = qrow + it * 32;
                *(__half2*)&As[np][r][qc4]     = __floats2half2_rn(pa[it].x, pa[it].y);
                *(__half2*)&As[np][r][qc4 + 2] = __floats2half2_rn(pa[it].z, pa[it].w);
                *(__half2*)&Ws[np][r][qc4]     = __floats2half2_rn(pw[it].x, pw[it].y);
                *(__half2*)&Ws[np][r][qc4 + 2] = __floats2half2_rn(pw[it].z, pw[it].w);
            }
            __syncthreads();
            p = np;
        }
    }

    #pragma unroll
    for (int i = 0; i < 4; i++) {
        int r0 = m0 + warp_m*64 + i*16 + lg;
        #pragma unroll
        for (int j = 0; j < 4; j++) {
            int cc = n0 + warp_n*32 + j*8 + lq*2;
            float b0 = bias[cc], b1 = bias[cc+1];
            out[(size_t)r0       * ND + cc    ] = acc[i][j][0] + b0;
            out[(size_t)r0       * ND + cc + 1] = acc[i][j][1] + b1;
            out[(size_t)(r0 + 8) * ND + cc    ] = acc[i][j][2] + b0;
            out[(size_t)(r0 + 8) * ND + cc + 1] = acc[i][j][3] + b1;
        }
    }
}

// ---------------------------------------------------------------------------
extern "C" void kernel_launch(void* const* d_in, const int* in_sizes, int n_in,
                              void* d_out, int out_size)
{
    const float* x     = (const float*)d_in[0];
    const float* A_log = (const float*)d_in[1];
    const float* Dvec  = (const float*)d_in[2];
    const float* B_w   = (const float*)d_in[3];
    const float* B_b   = (const float*)d_in[4];
    const float* C_w   = (const float*)d_in[5];
    const float* C_b   = (const float*)d_in[6];
    const float* dt_w  = (const float*)d_in[7];
    const float* dt_b  = (const float*)d_in[8];
    const float* out_w = (const float*)d_in[9];
    const float* out_b = (const float*)d_in[10];
    float* out = (float*)d_out;

    cudaFuncSetAttribute(y_kernel_tc, cudaFuncAttributeMaxDynamicSharedMemorySize,
                         Y_SMEM);

    proj_fused<<<dim3(NTOK/64, 3), 256>>>(x, B_w, B_b, C_w, C_b, dt_w, dt_b);
    cumsum_kernel<<<NB*NH*NC, NL>>>(A_log);
    states_tc<<<NB*NC*NH, 256>>>(x);
    scan_kernel<<<NB*NH*16, 256>>>();
    y_kernel_tc<<<NB*NC*NH*2, 256, Y_SMEM>>>(x, Dvec);
    out_gemm_f16<<<dim3(ND/128, NTOK/128), 256>>>(out_w, out_b, out);
}